// round 1
// baseline (speedup 1.0000x reference)
#include <cuda_runtime.h>
#include <math.h>

#define B  64
#define TF 64
#define TE 32
#define H  100
#define E  40
#define SP 256
#define EV 20000
#define M2 (B*TE)   // 2048 rows of final GEMM

// ---------------- device scratch (no runtime allocation allowed) ----------------
__device__ float g_h[B*H];            // encoder final state -> decoder h0
__device__ float g_enc[B*TF*H];       // encoder outputs
__device__ float g_encA[B*TF*200];    // enc @ att_W1[H:2H,:]
__device__ float g_encS[B*TF*SP];     // enc @ sp1_W[2H:3H,:]
__device__ float g_sp2m[SP+1];        // row-means of sp2_W, [SP]=mean(sp2_b)
__device__ float g_dec[B*TE*H];       // decoder outputs
__device__ float g_hidT[H*M2];        // relu(dec@ff1+b), TRANSPOSED [100][2048]
__device__ float g_rowm[M2];
__device__ float g_rows[M2];

__device__ __forceinline__ float sigmoidf_(float x){ return 1.0f/(1.0f+expf(-x)); }

// ---------------- encoder: CTA per batch, weights resident in smem ----------------
__global__ void k_encoder(const int* __restrict__ enc_in, const float* __restrict__ femb,
                          const float* __restrict__ W, const float* __restrict__ U,
                          const float* __restrict__ bias)
{
    extern __shared__ float sm[];
    float* sW  = sm;             // 40*300
    float* sU  = sW + E*300;     // 100*300
    float* sB  = sU + H*300;     // 600
    float* sH  = sB + 600;       // 100
    float* sX  = sH + H;         // 40
    float* sXs = sX + E;         // 300
    float* sHs = sXs + 300;      // 300
    int b = blockIdx.x, tid = threadIdx.x, nt = blockDim.x;

    for(int i=tid;i<E*300;i+=nt) sW[i]=W[i];
    for(int i=tid;i<H*300;i+=nt) sU[i]=U[i];
    for(int i=tid;i<600;  i+=nt) sB[i]=bias[i];
    if(tid<H) sH[tid]=0.f;
    __syncthreads();

    for(int t=0;t<TF;t++){
        int tok = enc_in[b*TF+t];
        if(tid<E) sX[tid]=femb[tok*E+tid];
        __syncthreads();
        if(tid<300){
            float a=sB[tid];
            #pragma unroll 8
            for(int k=0;k<E;k++) a += sX[k]*sW[k*300+tid];
            float c=sB[300+tid];
            #pragma unroll 10
            for(int k=0;k<H;k++) c += sH[k]*sU[k*300+tid];
            sXs[tid]=a; sHs[tid]=c;
        }
        __syncthreads();
        if(tid<H){
            float z    = sigmoidf_(sXs[tid]      + sHs[tid]);
            float r    = sigmoidf_(sXs[H+tid]    + sHs[H+tid]);
            float cand = tanhf   (sXs[2*H+tid]  + r*sHs[2*H+tid]);
            float hn   = z*sH[tid] + (1.f-z)*cand;
            sH[tid]=hn;
            g_enc[(b*TF+t)*H+tid]=hn;
        }
        __syncthreads();
    }
    if(tid<H) g_h[b*H+tid]=sH[tid];
}

// ---------------- precompute encA / encS ----------------
__global__ void k_pre(const float* __restrict__ attW1, const float* __restrict__ sp1W)
{
    __shared__ float sE[8*H];
    int r0 = blockIdx.x*8;             // grid 512 -> rows of [B*TF]
    int tid=threadIdx.x;
    for(int i=tid;i<8*H;i+=256) sE[i]=g_enc[r0*H+i];
    __syncthreads();
    for(int idx=tid; idx<8*456; idx+=256){
        int row = idx/456, d = idx-row*456;
        const float* e = sE + row*H;
        float acc=0.f;
        if(d<200){
            #pragma unroll 10
            for(int k=0;k<H;k++) acc += e[k]*attW1[(H+k)*200+d];
            g_encA[(r0+row)*200+d]=acc;
        } else {
            int dd=d-200;
            #pragma unroll 10
            for(int k=0;k<H;k++) acc += e[k]*sp1W[(2*H+k)*SP+dd];
            g_encS[(r0+row)*SP+dd]=acc;
        }
    }
}

// ---------------- row-means of sp2_W (absorbs the 2nd scratchpad matmul) ----------------
__global__ void k_sp2m(const float* __restrict__ sp2W, const float* __restrict__ sp2b)
{
    int k=threadIdx.x;
    float s=0.f;
    for(int j=0;j<SP;j++) s+=sp2W[k*SP+j];
    g_sp2m[k]=s*(1.f/SP);
    if(k==0){
        float t=0.f;
        for(int j=0;j<SP;j++) t+=sp2b[j];
        g_sp2m[SP]=t*(1.f/SP);
    }
}

// ---------------- decoder: persistent CTA per batch, all state in smem ----------------
__global__ void __launch_bounds__(512,1)
k_decoder(const float* __restrict__ attW1, const float* __restrict__ attW2,
          const float* __restrict__ decW,  const float* __restrict__ decU,
          const float* __restrict__ decb,  const float* __restrict__ sp1W,
          const float* __restrict__ sp1b)
{
    extern __shared__ float sm[];
    float* sEnc   = sm;                  // 6400
    float* sEncA  = sEnc  + TF*H;        // 12800
    float* sEncS  = sEncA + TF*200;      // 16384
    float* sH     = sEncS + TF*SP;       // 100
    float* sHn    = sH     + H;          // 100
    float* sRead  = sHn    + H;          // 100
    float* sHbA   = sRead  + H;          // 200
    float* sQ     = sHbA   + 200;        // 200
    float* sXs    = sQ     + 200;        // 300
    float* sHs    = sXs    + 300;        // 300
    float* sHrS   = sHs    + 300;        // 256
    float* sReadA = sHrS   + SP;         // 200
    float* sReadS = sReadA + 200;        // 256
    float* sAlpha = sReadS + SP;         // 64
    float* sScore = sAlpha + TF;         // 64
    float* sG     = sScore + TF;         // 64
    float* sSp1b  = sG     + TF;         // 256
    float* sSp2m  = sSp1b  + SP;         // 257

    int b=blockIdx.x, tid=threadIdx.x;
    int lane = tid&31, wid = tid>>5;     // 16 warps

    for(int i=tid;i<TF*H;  i+=512) sEnc[i] =g_enc [b*TF*H+i];
    for(int i=tid;i<TF*200;i+=512) sEncA[i]=g_encA[b*TF*200+i];
    for(int i=tid;i<TF*SP; i+=512) sEncS[i]=g_encS[b*TF*SP+i];
    if(tid<SP)   sSp1b[tid]=sp1b[tid];
    if(tid<SP+1) sSp2m[tid]=g_sp2m[tid];
    if(tid<H)    sH[tid]=g_h[b*H+tid];
    __syncthreads();

    for(int s=0;s<TE;s++){
        // A: hbA = h @ att_W1[0:H,:], query = h @ att_W2
        if(tid<200){
            float a=0.f,q=0.f;
            #pragma unroll 10
            for(int k=0;k<H;k++){ float hk=sH[k]; a+=hk*attW1[k*200+tid]; q+=hk*attW2[k*200+tid]; }
            sHbA[tid]=a; sQ[tid]=q;
        }
        __syncthreads();
        // B: scores[t] = sum_d tanh(hbA+encA) * query
        for(int tt=0;tt<4;tt++){
            int t = wid*4+tt;
            float p=0.f;
            for(int d=lane; d<200; d+=32)
                p += tanhf(sHbA[d]+sEncA[t*200+d]) * sQ[d];
            #pragma unroll
            for(int o=16;o;o>>=1) p+=__shfl_down_sync(0xffffffffu,p,o);
            if(lane==0) sScore[t]=p;
        }
        __syncthreads();
        // C: softmax over 64 scores (warp 0)
        if(wid==0){
            float s0=sScore[lane], s1=sScore[32+lane];
            float mx=fmaxf(s0,s1);
            #pragma unroll
            for(int o=16;o;o>>=1) mx=fmaxf(mx,__shfl_xor_sync(0xffffffffu,mx,o));
            float e0=expf(s0-mx), e1=expf(s1-mx);
            float su=e0+e1;
            #pragma unroll
            for(int o=16;o;o>>=1) su+=__shfl_xor_sync(0xffffffffu,su,o);
            float inv=1.f/su;
            sAlpha[lane]=e0*inv; sAlpha[32+lane]=e1*inv;
        }
        __syncthreads();
        // D: read = alpha . enc
        if(tid<H){
            float acc=0.f;
            #pragma unroll 8
            for(int t=0;t<TF;t++) acc += sAlpha[t]*sEnc[t*H+tid];
            sRead[tid]=acc;
        }
        __syncthreads();
        // E: GRU matvecs
        if(tid<300){
            float a=decb[tid], c=decb[300+tid];
            #pragma unroll 10
            for(int k=0;k<H;k++){ a+=sRead[k]*decW[k*300+tid]; c+=sH[k]*decU[k*300+tid]; }
            sXs[tid]=a; sHs[tid]=c;
        }
        __syncthreads();
        // F: GRU pointwise
        if(tid<H){
            float z    = sigmoidf_(sXs[tid]     + sHs[tid]);
            float r    = sigmoidf_(sXs[H+tid]   + sHs[H+tid]);
            float cand = tanhf   (sXs[2*H+tid] + r*sHs[2*H+tid]);
            float hn   = z*sH[tid] + (1.f-z)*cand;
            sHn[tid]=hn;
            g_dec[(b*TE+s)*H+tid]=hn;
        }
        __syncthreads();
        // G: hrS = hn@sp1a + read@sp1b + b ; readA = read@att_W1[H:2H]; readS = read@sp1c
        for(int idx=tid; idx<712; idx+=512){
            if(idx<SP){
                float acc=sSp1b[idx];
                #pragma unroll 10
                for(int j=0;j<H;j++) acc+=sHn[j]  *sp1W[j*SP+idx];
                #pragma unroll 10
                for(int j=0;j<H;j++) acc+=sRead[j]*sp1W[(H+j)*SP+idx];
                sHrS[idx]=acc;
            } else if(idx<456){
                int d=idx-SP;
                float acc=0.f;
                #pragma unroll 10
                for(int k=0;k<H;k++) acc+=sRead[k]*attW1[(H+k)*200+d];
                sReadA[d]=acc;
            } else {
                int kk=idx-456;
                float acc=0.f;
                #pragma unroll 10
                for(int j=0;j<H;j++) acc+=sRead[j]*sp1W[(2*H+j)*SP+kk];
                sReadS[kk]=acc;
            }
        }
        __syncthreads();
        // H: g[t] = sigmoid( relu(hrS+encS[t]) . sp2_rowmean + mean(sp2_b) )
        for(int tt=0;tt<4;tt++){
            int t=wid*4+tt;
            float p=0.f;
            #pragma unroll
            for(int k=lane;k<SP;k+=32){
                float v = sHrS[k]+sEncS[t*SP+k];
                p += fmaxf(v,0.f)*sSp2m[k];
            }
            #pragma unroll
            for(int o=16;o;o>>=1) p+=__shfl_down_sync(0xffffffffu,p,o);
            if(lane==0) sG[t]=sigmoidf_(p+sSp2m[SP]);
        }
        __syncthreads();
        // I: incremental state rewrite (exploits linearity of enc' = g*enc+(1-g)*read)
        for(int e=tid;e<TF*H;e+=512){
            int t=e/H, i=e-t*H;
            float g=sG[t];
            sEnc[e]=g*sEnc[e]+(1.f-g)*sRead[i];
        }
        for(int e=tid;e<TF*200;e+=512){
            int t=e/200, d=e-t*200;
            float g=sG[t];
            sEncA[e]=g*sEncA[e]+(1.f-g)*sReadA[d];
        }
        for(int e=tid;e<TF*SP;e+=512){
            int t=e>>8, k=e&255;
            float g=sG[t];
            sEncS[e]=g*sEncS[e]+(1.f-g)*sReadS[k];
        }
        __syncthreads();
        if(tid<H) sH[tid]=sHn[tid];
        __syncthreads();
    }
}

// ---------------- ff1 + relu, store transposed for GEMM coalescing ----------------
__global__ void k_ff1(const float* __restrict__ W, const float* __restrict__ bias)
{
    __shared__ float sRow[H];
    int m=blockIdx.x, tid=threadIdx.x;   // grid 2048, block 128
    if(tid<H) sRow[tid]=g_dec[m*H+tid];
    __syncthreads();
    if(tid<H){
        float acc=bias[tid];
        #pragma unroll 10
        for(int k=0;k<H;k++) acc+=sRow[k]*W[k*H+tid];
        g_hidT[tid*M2+m]=fmaxf(acc,0.f);
    }
}

// ---------------- final GEMM: [2048,100]@[100,20000] -> logits in d_out ----------------
__global__ void __launch_bounds__(256)
k_gemm(const float* __restrict__ ff2W, const float* __restrict__ ff2b, float* __restrict__ out)
{
    __shared__ float As[50*64];   // [k][m]
    __shared__ float Bs[50*64];   // [k][n]
    int n0=blockIdx.x*64, m0=blockIdx.y*64;
    int tid=threadIdx.x, tx=tid&15, ty=tid>>4;
    float acc[4][4]={};
    for(int kc=0;kc<H;kc+=50){
        for(int i=tid;i<50*64;i+=256){
            int k=kc+(i>>6), mn=i&63;
            As[i]=g_hidT[k*M2 + m0+mn];
            int gn=n0+mn;
            Bs[i]=(gn<EV)?ff2W[k*EV+gn]:0.f;
        }
        __syncthreads();
        #pragma unroll 5
        for(int k=0;k<50;k++){
            float4 av=*(const float4*)&As[k*64+ty*4];
            float4 bv=*(const float4*)&Bs[k*64+tx*4];
            float a[4]={av.x,av.y,av.z,av.w};
            float bb[4]={bv.x,bv.y,bv.z,bv.w};
            #pragma unroll
            for(int i=0;i<4;i++)
                #pragma unroll
                for(int j=0;j<4;j++) acc[i][j]+=a[i]*bb[j];
        }
        __syncthreads();
    }
    int gn=n0+tx*4;
    if(gn+3<EV){
        float4 bb=*(const float4*)&ff2b[gn];
        #pragma unroll
        for(int i=0;i<4;i++){
            int gm=m0+ty*4+i;
            float4 v;
            v.x=acc[i][0]+bb.x; v.y=acc[i][1]+bb.y;
            v.z=acc[i][2]+bb.z; v.w=acc[i][3]+bb.w;
            *(float4*)&out[(size_t)gm*EV+gn]=v;
        }
    }
}

// ---------------- softmax: row stats then normalize ----------------
__global__ void k_rowstat(const float* __restrict__ out)
{
    __shared__ float red[8];
    int row=blockIdx.x, tid=threadIdx.x, lane=tid&31, wid=tid>>5;
    const float4* p4=(const float4*)(out+(size_t)row*EV);
    float m=-1e30f;
    for(int j=tid;j<EV/4;j+=256){
        float4 v=p4[j];
        m=fmaxf(m,fmaxf(fmaxf(v.x,v.y),fmaxf(v.z,v.w)));
    }
    #pragma unroll
    for(int o=16;o;o>>=1) m=fmaxf(m,__shfl_xor_sync(0xffffffffu,m,o));
    if(lane==0) red[wid]=m;
    __syncthreads();
    if(tid<32){
        float v=(lane<8)?red[lane]:-1e30f;
        #pragma unroll
        for(int o=4;o;o>>=1) v=fmaxf(v,__shfl_xor_sync(0xffffffffu,v,o));
        if(lane==0) red[0]=v;
    }
    __syncthreads();
    m=red[0];
    __syncthreads();
    float s=0.f;
    for(int j=tid;j<EV/4;j+=256){
        float4 v=p4[j];
        s += expf(v.x-m)+expf(v.y-m)+expf(v.z-m)+expf(v.w-m);
    }
    #pragma unroll
    for(int o=16;o;o>>=1) s+=__shfl_xor_sync(0xffffffffu,s,o);
    if(lane==0) red[wid]=s;
    __syncthreads();
    if(tid==0){
        float v=0.f;
        for(int i=0;i<8;i++) v+=red[i];
        g_rowm[row]=m; g_rows[row]=v;
    }
}

__global__ void k_norm(float* __restrict__ out)
{
    int row=blockIdx.x, tid=threadIdx.x;
    float m=g_rowm[row], inv=1.f/g_rows[row];
    float4* p4=(float4*)(out+(size_t)row*EV);
    for(int j=tid;j<EV/4;j+=256){
        float4 v=p4[j];
        v.x=expf(v.x-m)*inv; v.y=expf(v.y-m)*inv;
        v.z=expf(v.z-m)*inv; v.w=expf(v.w-m)*inv;
        p4[j]=v;
    }
}

// ---------------- launch ----------------
extern "C" void kernel_launch(void* const* d_in, const int* in_sizes, int n_in,
                              void* d_out, int out_size)
{
    (void)in_sizes; (void)n_in; (void)out_size;
    const int*   enc_in=(const int*)  d_in[0];
    const float* femb  =(const float*)d_in[2];
    const float* encW  =(const float*)d_in[4];
    const float* encU  =(const float*)d_in[5];
    const float* encb  =(const float*)d_in[6];
    const float* decW  =(const float*)d_in[7];
    const float* decU  =(const float*)d_in[8];
    const float* decb  =(const float*)d_in[9];
    const float* attW1 =(const float*)d_in[10];
    const float* attW2 =(const float*)d_in[11];
    const float* sp1W  =(const float*)d_in[12];
    const float* sp1b  =(const float*)d_in[13];
    const float* sp2W  =(const float*)d_in[14];
    const float* sp2b  =(const float*)d_in[15];
    const float* ff1W  =(const float*)d_in[16];
    const float* ff1b  =(const float*)d_in[17];
    const float* ff2W  =(const float*)d_in[18];
    const float* ff2b  =(const float*)d_in[19];
    float* out=(float*)d_out;

    static const int ENC_SMEM = (E*300 + H*300 + 600 + H + E + 300 + 300)*4;       // 173360
    static const int DEC_SMEM = (TF*H + TF*200 + TF*SP + 2717)*4;                  // 153204

    cudaFuncSetAttribute(k_encoder, cudaFuncAttributeMaxDynamicSharedMemorySize, ENC_SMEM);
    cudaFuncSetAttribute(k_decoder, cudaFuncAttributeMaxDynamicSharedMemorySize, DEC_SMEM);

    k_encoder<<<B,320,ENC_SMEM>>>(enc_in,femb,encW,encU,encb);
    k_pre    <<<(B*TF)/8,256>>>(attW1,sp1W);
    k_sp2m   <<<1,SP>>>(sp2W,sp2b);
    k_decoder<<<B,512,DEC_SMEM>>>(attW1,attW2,decW,decU,decb,sp1W,sp1b);
    k_ff1    <<<M2,128>>>(ff1W,ff1b);
    k_gemm   <<<dim3((EV+63)/64, M2/64),256>>>(ff2W,ff2b,out);
    k_rowstat<<<M2,256>>>(out);
    k_norm   <<<M2,256>>>(out);
}